// round 16
// baseline (speedup 1.0000x reference)
#include <cuda_runtime.h>

// Problem constants (fixed by the reference)
#define B_     4
#define N_     4096
#define E_     128
#define CACHE_ 32
#define NK_    4
#define CE_    32      // channels per unit (E / NK)
#define M_     128     // N / CACHE
#define BNE_   (B_*N_*E_)
#define NW_    2       // warps per unit
#define CPW_   16      // channels per warp
#define KP_    8       // packed channel pairs per warp

// Inter-layer scratch (device globals: no allocation in kernel_launch)
__device__ float g_x [BNE_];
__device__ float g_xa[BNE_];

typedef unsigned long long u64;

__device__ __forceinline__ float tanh_fast(float x) {
    float y;
    asm("tanh.approx.f32 %0, %1;" : "=f"(y) : "f"(x));
    return y;
}
__device__ __forceinline__ float ex2_fast(float x) {
    float y;
    asm("ex2.approx.f32 %0, %1;" : "=f"(y) : "f"(x));
    return y;
}
__device__ __forceinline__ u64 pk(float lo, float hi) {
    u64 r; asm("mov.b64 %0, {%1, %2};" : "=l"(r) : "f"(lo), "f"(hi)); return r;
}
__device__ __forceinline__ void upk(u64 x, float& lo, float& hi) {
    asm("mov.b64 {%0, %1}, %2;" : "=f"(lo), "=f"(hi) : "l"(x));
}
__device__ __forceinline__ u64 fma2(u64 a, u64 b, u64 c) {
    u64 d; asm("fma.rn.f32x2 %0, %1, %2, %3;" : "=l"(d) : "l"(a), "l"(b), "l"(c)); return d;
}
__device__ __forceinline__ u64 mul2(u64 a, u64 b) {
    u64 d; asm("mul.rn.f32x2 %0, %1, %2;" : "=l"(d) : "l"(a), "l"(b)); return d;
}
__device__ __forceinline__ u64 add2(u64 a, u64 b) {
    u64 d; asm("add.rn.f32x2 %0, %1, %2;" : "=l"(d) : "l"(a), "l"(b)); return d;
}

// 2 warps per (b,g,n) unit (champion structure, R5/R6 lineage).
// MUFU.TANH is half-rate (rt~16) and is the hidden binder: 16 TANH/warp-step
// saturate the MUFU pipe. For even pairs compute
//   tanh(x) = 1 - 2/(e^{2x}+1)
// via EX2 (full-rate MUFU, rt 8) + division-free reciprocal:
//   bit-trick seed, then two sign-tracked Newton steps.
// R15 NaN fix: clamp the tanh argument to [-9, 9] BEFORE the EX2 — at |x|>9
// tanh is 1 to within 2.5e-8, and e^{18} stays finite so the bit-trick
// reciprocal seed remains valid (R15 overflowed e^{2x} to inf -> NaN).
__global__ void __launch_bounds__(64, 14)
ncn_layer(const float* __restrict__ X, const float* __restrict__ XA,
          const float* __restrict__ W,         // 256 floats: Wi[4][32], Wj[4][32]
          float* __restrict__ YX, float* __restrict__ YA,
          int s)                                // group-index stride (0 or 1)
{
    __shared__ float tile[CACHE_][CACHE_ + 1];
    __shared__ u64 ebuf[2][NW_][CACHE_];        // [parity][warp][lane] = (Ax_w,Bx_w)
    __shared__ __align__(16) u64 sW4[2 * (CE_ / 2)];  // (Wi2,Wj2) interleaved

    const int t    = threadIdx.x;
    const int w    = t >> 5;                    // warp in block (0/1)
    const int lane = t & 31;                    // row-in-group
    const int blk  = blockIdx.x;                // 0 .. 2047
    const int n    = blk & (NK_ - 1);
    const int g    = (blk >> 2) & (M_ - 1);
    const int b    = blk >> 9;

    if (t < CE_ / 2) {
        int c = n * CE_ + 2 * t;
        sW4[2 * t]     = pk(W[c],      W[c + 1]);       // (Wi_c0, Wi_c1)
        sW4[2 * t + 1] = pk(W[E_ + c], W[E_ + c + 1]);  // (Wj_c0, Wj_c1)
    }

    const long long bBase    = (long long)b * N_ * E_;
    const long long chanBase = (long long)n * CE_ + lane;
    const int cw = w * CPW_;                    // this warp's first channel
    const int kw = cw >> 1;                     // first weight-pair index
    const ulonglong2* sWv = reinterpret_cast<const ulonglong2*>(sW4);

    u64 u2[KP_], v2[KP_];

    // ---- gather xi tile: warp w loads rows [w*16, w*16+16), coalesced ----
    #pragma unroll
    for (int r = 0; r < CPW_; ++r) {
        int rr  = cw + r;
        int row = ((g + rr * s) & (M_ - 1)) * CACHE_ + rr;
        tile[rr][lane] = X[bBase + (long long)row * E_ + chanBase];
    }
    __syncthreads();
    #pragma unroll
    for (int k = 0; k < KP_; ++k)
        u2[k] = pk(0.5f * tile[lane][cw + 2 * k], 0.5f * tile[lane][cw + 2 * k + 1]);
    __syncthreads();

    // ---- gather xa tile ----
    #pragma unroll
    for (int r = 0; r < CPW_; ++r) {
        int rr  = cw + r;
        int row = ((g + rr * s) & (M_ - 1)) * CACHE_ + rr;
        tile[rr][lane] = XA[bBase + (long long)row * E_ + chanBase];
    }
    __syncthreads();
    #pragma unroll
    for (int k = 0; k < KP_; ++k)
        v2[k] = pk(0.5f * tile[lane][cw + 2 * k], 0.5f * tile[lane][cw + 2 * k + 1]);

    const u64 K09  = pk(0.9f,  0.9f);
    const u64 K01  = pk(0.1f,  0.1f);
    const u64 K009 = pk(0.09f, 0.09f);
    const u64 K001 = pk(0.01f, 0.01f);
    const u64 Km2  = pk(-2.f, -2.f);
    const u64 K2w  = pk(2.f, 2.f);
    const u64 Z    = pk(0.f, 0.f);

    // ---- initial partials: X2w=(Ax_w,Bx_w), A2w=(Aa_w,Ba_w) ----
    u64 X2w, A2w, P2;
    {
        u64 ax = Z, bx = Z, aa = Z, ba = Z;
        #pragma unroll
        for (int k = 0; k < KP_; ++k) {
            ulonglong2 ww = sWv[kw + k];        // (Wi2, Wj2)
            ax = fma2(u2[k], ww.x, ax);
            bx = fma2(u2[k], ww.y, bx);
            aa = fma2(v2[k], ww.x, aa);
            ba = fma2(v2[k], ww.y, ba);
        }
        float l, h, Ax, Bx, Aa, Ba;
        upk(ax, l, h); Ax = 2.f * (l + h);
        upk(bx, l, h); Bx = 2.f * (l + h);
        upk(aa, l, h); Aa = 2.f * (l + h);
        upk(ba, l, h); Ba = 2.f * (l + h);
        X2w = pk(Ax, Bx);
        A2w = pk(Aa, Ba);
        P2  = fma2(X2w, K09, mul2(A2w, K009));  // .9X + .09A for step 0
    }
    ebuf[0][w][lane] = X2w;                     // publish for step 0
    __syncthreads();

    float sc = 1.0f;                  // 0.9^j
    float cj = 0.05f / 0.9f;          // 0.05 / 0.9^(j+1)

    // ---- 32-step recurrence ----
    #pragma unroll 1
    for (int j = 0; j < CACHE_; ++j) {
        const int p = j & 1;

        // sim = Ax_tot[lane] + Bx_tot[j]   (lean path: add2 + one shfl)
        u64 oth  = ebuf[p][1 - w][lane];
        u64 tot2 = add2(X2w, oth);
        float Axt, Bxt; upk(tot2, Axt, Bxt);
        float sim = Axt + __shfl_sync(0xffffffffu, Bxt, j);

        u64 sim2 = pk(sim, sim);
        u64 s2   = pk(sc, sc);
        u64 c2   = pk(cj, cj);
        u64 SA = Z, SB = Z, DA = Z, DB = Z;     // pair-split dot partials
        #pragma unroll
        for (int k = 0; k < KP_; ++k) {
            u64 uj = __shfl_sync(0xffffffffu, u2[k], j);    // pre-update row j
            u64 T  = mul2(s2, fma2(sim2, uj, u2[k]));       // true-scale T
            float t0, t1; upk(T, t0, t1);
            u64 F;
            if ((k & 1) == 0) {
                // EX2-based tanh: F = 1 - 2/(e^{2x}+1), arg clamped to [-9,9]
                float c0 = fminf(fmaxf(t0, -9.f), 9.f);
                float c1 = fminf(fmaxf(t1, -9.f), 9.f);
                float e0 = ex2_fast(c0 * 2.8853900817779268f);
                float e1 = ex2_fast(c1 * 2.8853900817779268f);
                float d0 = e0 + 1.f, d1 = e1 + 1.f;
                float r0 = __int_as_float(0x7EF311C3 - __float_as_int(d0));
                float r1 = __int_as_float(0x7EF311C3 - __float_as_int(d1));
                u64 d = pk(d0, d1);
                u64 r = pk(r0, r1);
                u64 e = fma2(d, r, Km2); r = mul2(r, e);    // r -> -refined
                e = fma2(d, r, K2w);     r = mul2(r, e);    // r -> -1/d refined
                float q0, q1; upk(r, q0, q1);
                F = pk(fmaf(q0, 2.f, 1.f), fmaf(q1, 2.f, 1.f));  // 1 + 2r
            } else {
                F = pk(tanh_fast(t0), tanh_fast(t1));
            }
            ulonglong2 ww = sWv[kw + k];                     // one LDS.128
            if (k & 1) { SB = fma2(F, ww.x, SB); DB = fma2(F, ww.y, DB); }
            else       { SA = fma2(F, ww.x, SA); DA = fma2(F, ww.y, DA); }
            v2[k] = fma2(c2,  F,     v2[k]);                // ~xa update
            u2[k] = fma2(K01, v2[k], u2[k]);                // ~xi update
        }
        float l, h, SF, DF;
        { u64 q = add2(SA, SB); upk(q, l, h); SF = l + h; }
        { u64 q = add2(DA, DB); upk(q, l, h); DF = l + h; }
        u64 S2 = pk(SF, DF);

        X2w = fma2(S2, K001, P2);                           // X' = .9X+.09A+.01S
        ebuf[p ^ 1][w][lane] = X2w;                         // publish (STS.64)
        A2w = fma2(A2w, K09, mul2(S2, K01));                // off-chain
        P2  = fma2(X2w, K09, mul2(A2w, K009));              // for next step
        __syncthreads();                                    // one bar per step

        sc *= 0.9f;
        cj *= (1.0f / 0.9f);
    }

    const float fscale = 2.0f * sc;   // undo half-scale and 0.9^32 rescale

    // ---- scatter yi ----
    #pragma unroll
    for (int k = 0; k < KP_; ++k) {
        float l, h; upk(u2[k], l, h);
        tile[lane][cw + 2 * k]     = fscale * l;
        tile[lane][cw + 2 * k + 1] = fscale * h;
    }
    __syncthreads();
    #pragma unroll
    for (int r = 0; r < CPW_; ++r) {
        int rr  = cw + r;
        int row = ((g + rr * s) & (M_ - 1)) * CACHE_ + rr;
        YX[bBase + (long long)row * E_ + chanBase] = tile[rr][lane];
    }
    __syncthreads();

    // ---- scatter ya ----
    #pragma unroll
    for (int k = 0; k < KP_; ++k) {
        float l, h; upk(v2[k], l, h);
        tile[lane][cw + 2 * k]     = fscale * l;
        tile[lane][cw + 2 * k + 1] = fscale * h;
    }
    __syncthreads();
    #pragma unroll
    for (int r = 0; r < CPW_; ++r) {
        int rr  = cw + r;
        int row = ((g + rr * s) & (M_ - 1)) * CACHE_ + rr;
        YA[bBase + (long long)row * E_ + chanBase] = tile[rr][lane];
    }
}

extern "C" void kernel_launch(void* const* d_in, const int* in_sizes, int n_in,
                              void* d_out, int out_size) {
    const float* x  = (const float*)d_in[0];
    const float* xa = (const float*)d_in[1];
    const float* W  = (const float*)d_in[2];
    float* out = (float*)d_out;

    float *gx = nullptr, *gxa = nullptr;
    cudaGetSymbolAddress((void**)&gx,  g_x);
    cudaGetSymbolAddress((void**)&gxa, g_xa);

    dim3 grid(B_ * M_ * NK_);   // 2048 blocks
    dim3 block(64);             // 2 warps per unit

    // Layer 0: stage shift s = 0 (contiguous groups)
    ncn_layer<<<grid, block>>>(x, xa, W, gx, gxa, 0);
    // Layer 1: stage shift s = 1 (block = (g + o) % m), writes final output
    ncn_layer<<<grid, block>>>(gx, gxa, W + 2 * E_, out, out + BNE_, 1);
}